// round 4
// baseline (speedup 1.0000x reference)
#include <cuda_runtime.h>
#include <cuda_bf16.h>
#include <cstdint>

#define TOKENS 4096
#define DM 1024
#define DF 4096
#define NE 8

typedef __nv_bfloat16 bf16;

// ---------------- device scratch (static, no runtime alloc) ----------------
__device__ int g_cnt[NE];
__device__ int g_tok[NE][TOKENS];
__device__ int g_slot[NE][TOKENS];
__device__ __align__(16) bf16 g_xh[(size_t)TOKENS * DM];
__device__ __align__(16) bf16 g_xl[(size_t)TOKENS * DM];
__device__ __align__(16) bf16 g_w1h[(size_t)NE * DF * DM];   // [E][N=DF][K=DM]
__device__ __align__(16) bf16 g_w1l[(size_t)NE * DF * DM];
__device__ __align__(16) bf16 g_w2h[(size_t)NE * DM * DF];   // [E][N=DM][K=DF]
__device__ __align__(16) bf16 g_w2l[(size_t)NE * DM * DF];
__device__ __align__(16) bf16 g_hh[(size_t)NE * TOKENS * DF];
__device__ __align__(16) bf16 g_hl[(size_t)NE * TOKENS * DF];
__device__ __align__(16) float g_buf[(size_t)2 * TOKENS * DM];

// ---------------- helpers ----------------
__device__ __forceinline__ uint32_t smem_u32(const void* p) {
    uint32_t a;
    asm("{ .reg .u64 t; cvta.to.shared.u64 t, %1; cvt.u32.u64 %0, t; }" : "=r"(a) : "l"(p));
    return a;
}
__device__ __forceinline__ void cp16(uint32_t s, const void* g) {
    asm volatile("cp.async.cg.shared.global [%0], [%1], 16;" :: "r"(s), "l"(g) : "memory");
}
__device__ __forceinline__ void cp_commit() {
    asm volatile("cp.async.commit_group;" ::: "memory");
}
__device__ __forceinline__ void cp_wait1() {
    asm volatile("cp.async.wait_group 1;" ::: "memory");
}
#define MMA_BF16(acc, a, b)                                                      \
    asm volatile(                                                                \
        "mma.sync.aligned.m16n8k16.row.col.f32.bf16.bf16.f32 "                   \
        "{%0,%1,%2,%3},{%4,%5,%6,%7},{%8,%9},{%0,%1,%2,%3};"                     \
        : "+f"((acc)[0]), "+f"((acc)[1]), "+f"((acc)[2]), "+f"((acc)[3])         \
        : "r"((a)[0]), "r"((a)[1]), "r"((a)[2]), "r"((a)[3]),                    \
          "r"((b)[0]), "r"((b)[1]))
#define LDSM4(r0, r1, r2, r3, addr)                                              \
    asm volatile("ldmatrix.sync.aligned.m8n8.x4.shared.b16 {%0,%1,%2,%3}, [%4];" \
                 : "=r"(r0), "=r"(r1), "=r"(r2), "=r"(r3) : "r"(addr))

__device__ __forceinline__ void split2(float a, float b, __nv_bfloat162& h, __nv_bfloat162& l) {
    bf16 ha = __float2bfloat16_rn(a);
    bf16 hb = __float2bfloat16_rn(b);
    h.x = ha; h.y = hb;
    l.x = __float2bfloat16_rn(a - __bfloat162float(ha));
    l.y = __float2bfloat16_rn(b - __bfloat162float(hb));
}

// ---------------- 0) zero counters ----------------
__global__ void zero_cnt_kernel() {
    if (threadIdx.x < NE) g_cnt[threadIdx.x] = 0;
}

// ---------------- 1) routing ----------------
__global__ void route_kernel(const float* __restrict__ x,
                             const float* __restrict__ Wg,
                             const float* __restrict__ bg) {
    int warp = threadIdx.x >> 5;
    int lane = threadIdx.x & 31;
    int token = blockIdx.x * 8 + warp;
    if (token >= TOKENS) return;

    float acc[NE];
#pragma unroll
    for (int e = 0; e < NE; e++) acc[e] = 0.f;
    const float* xrow = x + (size_t)token * DM;
    for (int k = lane; k < DM; k += 32) {
        float xv = xrow[k];
        const float* wr = Wg + (size_t)k * NE;
#pragma unroll
        for (int e = 0; e < NE; e++) acc[e] += xv * wr[e];
    }
#pragma unroll
    for (int e = 0; e < NE; e++)
#pragma unroll
        for (int o = 16; o > 0; o >>= 1)
            acc[e] += __shfl_xor_sync(0xffffffffu, acc[e], o);
    if (lane == 0) {
        float lg[NE];
#pragma unroll
        for (int e = 0; e < NE; e++) lg[e] = acc[e] + bg[e];
        int e0 = 0;
#pragma unroll
        for (int e = 1; e < NE; e++) if (lg[e] > lg[e0]) e0 = e;
        int e1 = (e0 == 0) ? 1 : 0;
#pragma unroll
        for (int e = 0; e < NE; e++) if (e != e0 && lg[e] > lg[e1]) e1 = e;
        int p0 = atomicAdd(&g_cnt[e0], 1);
        g_tok[e0][p0] = token; g_slot[e0][p0] = 0;
        int p1 = atomicAdd(&g_cnt[e1], 1);
        g_tok[e1][p1] = token; g_slot[e1][p1] = 1;
    }
}

// ---------------- 2) fp32 -> bf16 hi/lo converts ----------------
__global__ void convert_x_kernel(const float* __restrict__ x) {
    int i = blockIdx.x * blockDim.x + threadIdx.x;   // float4 index
    float4 v = ((const float4*)x)[i];
    __nv_bfloat162 h0, l0, h1, l1;
    split2(v.x, v.y, h0, l0);
    split2(v.z, v.w, h1, l1);
    ((__nv_bfloat162*)g_xh)[2 * i]     = h0;
    ((__nv_bfloat162*)g_xh)[2 * i + 1] = h1;
    ((__nv_bfloat162*)g_xl)[2 * i]     = l0;
    ((__nv_bfloat162*)g_xl)[2 * i + 1] = l1;
}

// transpose + split: W [E][K][N] fp32 -> [E][N][K] bf16 hi/lo
template <int K, int N, bool W1SEL>
__global__ void convert_w_kernel(const float* __restrict__ W) {
    __shared__ float t[32][33];
    bf16* Oh = W1SEL ? g_w1h : g_w2h;
    bf16* Ol = W1SEL ? g_w1l : g_w2l;
    int e = blockIdx.z;
    int n0 = blockIdx.x * 32, k0 = blockIdx.y * 32;
    int tx = threadIdx.x, ty = threadIdx.y;  // 32 x 8
    const float* Wp = W + (size_t)e * K * N;
#pragma unroll
    for (int i = 0; i < 4; i++)
        t[ty + 8 * i][tx] = Wp[(size_t)(k0 + ty + 8 * i) * N + n0 + tx];
    __syncthreads();
    bf16* oh = Oh + (size_t)e * N * K;
    bf16* ol = Ol + (size_t)e * N * K;
#pragma unroll
    for (int i = 0; i < 4; i++) {
        float v = t[tx][ty + 8 * i];
        bf16 h = __float2bfloat16_rn(v);
        bf16 l = __float2bfloat16_rn(v - __bfloat162float(h));
        size_t o = (size_t)(n0 + ty + 8 * i) * K + k0 + tx;
        oh[o] = h; ol[o] = l;
    }
}

// ---------------- 3) split-bf16 HMMA grouped GEMM ----------------
// BM=128, BN=128, BK=32. 256 threads = 8 warps (2 M x 4 N), warp tile 64x32.
// SMEM stage: Ah | Al | Bh | Bl, each 128 rows x 40 bf16 (80B padded rows).
// 3-stage cp.async pipeline, wait_group 1. ldmatrix.x4 fragment loads.
#define ROWB   80
#define TILEB  (128 * ROWB)          // 10240 B
#define STAGEB (4 * TILEB)           // 40960 B
#define NSTAGE 3
#define SMEMB  (NSTAGE * STAGEB + 512)

template <int KDIM>
__device__ __forceinline__ void stage_load(uint32_t sb, int k0,
                                           const bf16* __restrict__ Ah, const bf16* __restrict__ Al,
                                           const bf16* __restrict__ Bh, const bf16* __restrict__ Bl,
                                           const int* __restrict__ srow, int n0, int tid) {
#pragma unroll
    for (int half = 0; half < 2; half++) {
        int c = tid + half * 256;        // 0..511
        int r = c >> 2, j = c & 3;
        uint32_t so = (uint32_t)(r * ROWB + j * 16);
        size_t ga = (size_t)srow[r] * KDIM + k0 + j * 8;
        size_t gb = (size_t)(n0 + r) * KDIM + k0 + j * 8;
        cp16(sb + so,             Ah + ga);
        cp16(sb + TILEB + so,     Al + ga);
        cp16(sb + 2 * TILEB + so, Bh + gb);
        cp16(sb + 3 * TILEB + so, Bl + gb);
    }
}

template <int KDIM, int NDIM, bool G1>
__global__ void __launch_bounds__(256, 1)
moe_gemm(const float* __restrict__ bias) {
    const int e = blockIdx.z;
    const int cnt = g_cnt[e];
    const int m0 = blockIdx.y * 128;
    if (m0 >= cnt) return;
    const int n0 = blockIdx.x * 128;
    constexpr int NT = KDIM / 32;

    extern __shared__ char smem[];
    const uint32_t sb = smem_u32(smem);
    const int tid = threadIdx.x, wid = tid >> 5, lane = tid & 31;
    const int warp_m = wid >> 2, warp_n = wid & 3;
    const int g = lane >> 2, tg = lane & 3;
    int* srow = (int*)(smem + NSTAGE * STAGEB);

    if (tid < 128) {
        int rr = min(m0 + tid, cnt - 1);
        srow[tid] = G1 ? g_tok[e][rr] : (e * TOKENS + rr);
    }
    __syncthreads();

    const bf16* Ah = G1 ? g_xh : g_hh;
    const bf16* Al = G1 ? g_xl : g_hl;
    const bf16* Bh = (G1 ? g_w1h : g_w2h) + (size_t)e * NDIM * KDIM;
    const bf16* Bl = (G1 ? g_w1l : g_w2l) + (size_t)e * NDIM * KDIM;

    float acc[4][4][4];
#pragma unroll
    for (int i = 0; i < 4; i++)
#pragma unroll
        for (int j = 0; j < 4; j++)
#pragma unroll
            for (int k = 0; k < 4; k++) acc[i][j][k] = 0.f;

    // prologue: stages 0 and 1 in flight
    stage_load<KDIM>(sb, 0, Ah, Al, Bh, Bl, srow, n0, tid);
    cp_commit();
    stage_load<KDIM>(sb + STAGEB, 32, Ah, Al, Bh, Bl, srow, n0, tid);
    cp_commit();

    // ldmatrix per-lane base: lanes 0-15 -> rows lrow (k-lo half),
    // lanes 16-31 -> rows lrow (k-hi half, +16B)
    const int lrow = lane & 15;
    const uint32_t khoff = (lane >> 4) * 16;
    const uint32_t aOffBase = (uint32_t)((warp_m * 64 + lrow) * ROWB) + khoff;
    const uint32_t bOffBase = (uint32_t)(2 * TILEB + (warp_n * 32 + lrow) * ROWB) + khoff;

    int slot = 0;
    for (int it = 0; it < NT; it++) {
        cp_wait1();                 // oldest group (stage `it`) complete
        __syncthreads();
        if (it + 2 < NT) {
            int ns = slot + 2; if (ns >= NSTAGE) ns -= NSTAGE;
            stage_load<KDIM>(sb + ns * STAGEB, (it + 2) * 32,
                             Ah, Al, Bh, Bl, srow, n0, tid);
        }
        cp_commit();                // unconditional: keeps pending count exact

        const uint32_t st = sb + slot * STAGEB;
#pragma unroll
        for (int ks = 0; ks < 2; ks++) {
            const uint32_t kb = ks * 32;
            uint32_t ah[4][4], al[4][4], bh[4][2], bl[4][2];
#pragma unroll
            for (int mf = 0; mf < 4; mf++) {
                uint32_t ad = st + aOffBase + mf * (16 * ROWB) + kb;
                LDSM4(ah[mf][0], ah[mf][1], ah[mf][2], ah[mf][3], ad);
                LDSM4(al[mf][0], al[mf][1], al[mf][2], al[mf][3], ad + TILEB);
            }
#pragma unroll
            for (int p = 0; p < 2; p++) {
                uint32_t bd = st + bOffBase + p * (16 * ROWB) + kb;
                LDSM4(bh[2 * p][0], bh[2 * p + 1][0], bh[2 * p][1], bh[2 * p + 1][1], bd);
                LDSM4(bl[2 * p][0], bl[2 * p + 1][0], bl[2 * p][1], bl[2 * p + 1][1], bd + TILEB);
            }
#pragma unroll
            for (int mf = 0; mf < 4; mf++)
#pragma unroll
                for (int nf = 0; nf < 4; nf++) {
                    MMA_BF16(acc[mf][nf], ah[mf], bh[nf]);
                    MMA_BF16(acc[mf][nf], ah[mf], bl[nf]);
                    MMA_BF16(acc[mf][nf], al[mf], bh[nf]);
                }
        }
        __syncthreads();
        slot++; if (slot >= NSTAGE) slot = 0;
    }

    // ---------------- epilogue ----------------
#pragma unroll
    for (int mf = 0; mf < 4; mf++) {
        int r0 = m0 + warp_m * 64 + mf * 16 + g;
        int r1 = r0 + 8;
#pragma unroll
        for (int nf = 0; nf < 4; nf++) {
            int col = n0 + warp_n * 32 + nf * 8 + tg * 2;
            float bv0 = bias[e * NDIM + col];
            float bv1 = bias[e * NDIM + col + 1];
#pragma unroll
            for (int h = 0; h < 2; h++) {
                int r = h ? r1 : r0;
                if (r >= cnt) continue;
                float v0 = acc[mf][nf][2 * h]     + bv0;
                float v1 = acc[mf][nf][2 * h + 1] + bv1;
                if (G1) {
                    v0 = fmaxf(v0, 0.f);
                    v1 = fmaxf(v1, 0.f);
                    __nv_bfloat162 hh, ll;
                    split2(v0, v1, hh, ll);
                    size_t o = ((size_t)(e * TOKENS + r)) * DF + col;
                    *(__nv_bfloat162*)(g_hh + o) = hh;
                    *(__nv_bfloat162*)(g_hl + o) = ll;
                } else {
                    int token = g_tok[e][r];
                    int slot2 = g_slot[e][r];
                    float* dst = g_buf + ((size_t)slot2 * TOKENS + token) * DM + col;
                    *(float2*)dst = make_float2(v0, v1);
                }
            }
        }
    }
}

// ---------------- 4) combine ----------------
__global__ void combine_kernel(float* __restrict__ out) {
    int i = blockIdx.x * blockDim.x + threadIdx.x;
    const float4* b0 = (const float4*)g_buf;
    const float4* b1 = (const float4*)(g_buf + (size_t)TOKENS * DM);
    float4 u = b0[i], v = b1[i];
    ((float4*)out)[i] = make_float4(u.x + v.x, u.y + v.y, u.z + v.z, u.w + v.w);
}

// ---------------- host ----------------
extern "C" void kernel_launch(void* const* d_in, const int* in_sizes, int n_in,
                              void* d_out, int out_size) {
    const float* x  = (const float*)d_in[0];
    const float* Wg = (const float*)d_in[1];
    const float* bg = (const float*)d_in[2];
    const float* W1 = (const float*)d_in[3];
    const float* b1 = (const float*)d_in[4];
    const float* W2 = (const float*)d_in[5];
    const float* b2 = (const float*)d_in[6];
    float* out = (float*)d_out;

    cudaFuncSetAttribute(moe_gemm<DM, DF, true>,
                         cudaFuncAttributeMaxDynamicSharedMemorySize, SMEMB);
    cudaFuncSetAttribute(moe_gemm<DF, DM, false>,
                         cudaFuncAttributeMaxDynamicSharedMemorySize, SMEMB);

    zero_cnt_kernel<<<1, 32>>>();
    route_kernel<<<TOKENS / 8, 256>>>(x, Wg, bg);

    convert_x_kernel<<<TOKENS * DM / 4 / 256, 256>>>(x);
    convert_w_kernel<DM, DF, true><<<dim3(DF / 32, DM / 32, NE), dim3(32, 8)>>>(W1);
    convert_w_kernel<DF, DM, false><<<dim3(DM / 32, DF / 32, NE), dim3(32, 8)>>>(W2);

    // GEMM1: h = relu(gather(x) @ W1[e] + b1[e]) -> g_hh/g_hl
    moe_gemm<DM, DF, true><<<dim3(DF / 128, TOKENS / 128, NE), 256, SMEMB>>>(b1);
    // GEMM2: y = h @ W2[e] + b2[e] -> scatter into g_buf
    moe_gemm<DF, DM, false><<<dim3(DM / 128, TOKENS / 128, NE), 256, SMEMB>>>(b2);

    combine_kernel<<<(TOKENS * DM / 4) / 256, 256>>>(out);
}

// round 5
// speedup vs baseline: 1.2636x; 1.2636x over previous
#include <cuda_runtime.h>
#include <cuda_bf16.h>
#include <cstdint>

#define TOKENS 4096
#define DM 1024
#define DF 4096
#define NE 8

typedef __nv_bfloat16 bf16;

// ---------------- device scratch (static, no runtime alloc) ----------------
__device__ int g_cnt[NE];
__device__ int g_tok[NE][TOKENS];
__device__ int g_slot[NE][TOKENS];
__device__ __align__(16) bf16 g_xh[(size_t)TOKENS * DM];
__device__ __align__(16) bf16 g_xl[(size_t)TOKENS * DM];
__device__ __align__(16) bf16 g_w1h[(size_t)NE * DF * DM];   // [E][N=DF][K=DM]
__device__ __align__(16) bf16 g_w1l[(size_t)NE * DF * DM];
__device__ __align__(16) bf16 g_w2h[(size_t)NE * DM * DF];   // [E][N=DM][K=DF]
__device__ __align__(16) bf16 g_w2l[(size_t)NE * DM * DF];
__device__ __align__(16) bf16 g_hh[(size_t)NE * TOKENS * DF];
__device__ __align__(16) bf16 g_hl[(size_t)NE * TOKENS * DF];
__device__ __align__(16) float g_buf[(size_t)2 * TOKENS * DM];

// ---------------- helpers ----------------
__device__ __forceinline__ uint32_t smem_u32(const void* p) {
    uint32_t a;
    asm("{ .reg .u64 t; cvta.to.shared.u64 t, %1; cvt.u32.u64 %0, t; }" : "=r"(a) : "l"(p));
    return a;
}
__device__ __forceinline__ void cp16(uint32_t s, const void* g) {
    asm volatile("cp.async.cg.shared.global [%0], [%1], 16;" :: "r"(s), "l"(g) : "memory");
}
__device__ __forceinline__ void cp_commit() {
    asm volatile("cp.async.commit_group;" ::: "memory");
}
__device__ __forceinline__ void cp_wait0() {
    asm volatile("cp.async.wait_group 0;" ::: "memory");
}
#define MMA_BF16(acc, a, b)                                                      \
    asm volatile(                                                                \
        "mma.sync.aligned.m16n8k16.row.col.f32.bf16.bf16.f32 "                   \
        "{%0,%1,%2,%3},{%4,%5,%6,%7},{%8,%9},{%0,%1,%2,%3};"                     \
        : "+f"((acc)[0]), "+f"((acc)[1]), "+f"((acc)[2]), "+f"((acc)[3])         \
        : "r"((a)[0]), "r"((a)[1]), "r"((a)[2]), "r"((a)[3]),                    \
          "r"((b)[0]), "r"((b)[1]))

__device__ __forceinline__ void split2(float a, float b, __nv_bfloat162& h, __nv_bfloat162& l) {
    bf16 ha = __float2bfloat16_rn(a);
    bf16 hb = __float2bfloat16_rn(b);
    h.x = ha; h.y = hb;
    l.x = __float2bfloat16_rn(a - __bfloat162float(ha));
    l.y = __float2bfloat16_rn(b - __bfloat162float(hb));
}

// ---------------- 0) zero counters ----------------
__global__ void zero_cnt_kernel() {
    if (threadIdx.x < NE) g_cnt[threadIdx.x] = 0;
}

// ---------------- 1) routing ----------------
__global__ void route_kernel(const float* __restrict__ x,
                             const float* __restrict__ Wg,
                             const float* __restrict__ bg) {
    int warp = threadIdx.x >> 5;
    int lane = threadIdx.x & 31;
    int token = blockIdx.x * 8 + warp;
    if (token >= TOKENS) return;

    float acc[NE];
#pragma unroll
    for (int e = 0; e < NE; e++) acc[e] = 0.f;
    const float* xrow = x + (size_t)token * DM;
    for (int k = lane; k < DM; k += 32) {
        float xv = xrow[k];
        const float* wr = Wg + (size_t)k * NE;
#pragma unroll
        for (int e = 0; e < NE; e++) acc[e] += xv * wr[e];
    }
#pragma unroll
    for (int e = 0; e < NE; e++)
#pragma unroll
        for (int o = 16; o > 0; o >>= 1)
            acc[e] += __shfl_xor_sync(0xffffffffu, acc[e], o);
    if (lane == 0) {
        float lg[NE];
#pragma unroll
        for (int e = 0; e < NE; e++) lg[e] = acc[e] + bg[e];
        int e0 = 0;
#pragma unroll
        for (int e = 1; e < NE; e++) if (lg[e] > lg[e0]) e0 = e;
        int e1 = (e0 == 0) ? 1 : 0;
#pragma unroll
        for (int e = 0; e < NE; e++) if (e != e0 && lg[e] > lg[e1]) e1 = e;
        int p0 = atomicAdd(&g_cnt[e0], 1);
        g_tok[e0][p0] = token; g_slot[e0][p0] = 0;
        int p1 = atomicAdd(&g_cnt[e1], 1);
        g_tok[e1][p1] = token; g_slot[e1][p1] = 1;
    }
}

// ---------------- 2) fp32 -> bf16 hi/lo converts ----------------
__global__ void convert_x_kernel(const float* __restrict__ x) {
    int i = blockIdx.x * blockDim.x + threadIdx.x;   // float4 index
    float4 v = ((const float4*)x)[i];
    __nv_bfloat162 h0, l0, h1, l1;
    split2(v.x, v.y, h0, l0);
    split2(v.z, v.w, h1, l1);
    ((__nv_bfloat162*)g_xh)[2 * i]     = h0;
    ((__nv_bfloat162*)g_xh)[2 * i + 1] = h1;
    ((__nv_bfloat162*)g_xl)[2 * i]     = l0;
    ((__nv_bfloat162*)g_xl)[2 * i + 1] = l1;
}

// transpose + split: W [E][K][N] fp32 -> [E][N][K] bf16 hi/lo
// 32x32 tile; each thread emits 2 consecutive k as one bf162 store.
template <int K, int N, bool W1SEL>
__global__ void convert_w_kernel(const float* __restrict__ W) {
    __shared__ float t[32][33];
    bf16* Oh = W1SEL ? g_w1h : g_w2h;
    bf16* Ol = W1SEL ? g_w1l : g_w2l;
    int e = blockIdx.z;
    int n0 = blockIdx.x * 32, k0 = blockIdx.y * 32;
    int tx = threadIdx.x, ty = threadIdx.y;  // 32 x 8
    const float* Wp = W + (size_t)e * K * N;
#pragma unroll
    for (int i = 0; i < 4; i++)
        t[ty + 8 * i][tx] = Wp[(size_t)(k0 + ty + 8 * i) * N + n0 + tx];
    __syncthreads();
    bf16* oh = Oh + (size_t)e * N * K;
    bf16* ol = Ol + (size_t)e * N * K;
    // thread -> n-row = (tx&15)*2 rows? keep simple: each thread does 2 k at
    // (n = ty*4 + tx/8, k pair = (tx%8)*2 ... ) — instead: remap lanes.
    int n_l = (threadIdx.y * 4) + (tx >> 3);        // 0..31
    int k_l = (tx & 7) * 2;                          // even k, pairs
#pragma unroll
    for (int rep = 0; rep < 2; rep++) {
        int kk = k_l + rep * 16;
        float v0 = t[kk][n_l];
        float v1 = t[kk + 1][n_l];
        __nv_bfloat162 h, l;
        split2(v0, v1, h, l);
        size_t o = (size_t)(n0 + n_l) * K + k0 + kk;
        *(__nv_bfloat162*)(oh + o) = h;
        *(__nv_bfloat162*)(ol + o) = l;
    }
}

// ---------------- 3) split-bf16 HMMA grouped GEMM ----------------
// BM=128, BN=128, BK=32. 256 threads = 8 warps (2 M x 4 N), warp tile 64x32.
// SMEM stage: Ah | Al | Bh | Bl, each 128 rows x 40 bf16 (80B padded rows).
// 2-stage cp.async (R3-proven), occupancy 2, low-liveness fragment loop.
#define ROWB   80
#define TILEB  (128 * ROWB)          // 10240 B
#define STAGEB (4 * TILEB)           // 40960 B
#define SMEMB  (2 * STAGEB + 512)    // 82432 B; 2 CTAs = 165KB < 228KB

template <int KDIM>
__device__ __forceinline__ void stage_load(uint32_t sb, int k0,
                                           const bf16* __restrict__ Ah, const bf16* __restrict__ Al,
                                           const bf16* __restrict__ Bh, const bf16* __restrict__ Bl,
                                           const int* __restrict__ srow, int n0, int tid) {
#pragma unroll
    for (int half = 0; half < 2; half++) {
        int c = tid + half * 256;        // 0..511
        int r = c >> 2, j = c & 3;
        uint32_t so = (uint32_t)(r * ROWB + j * 16);
        size_t ga = (size_t)srow[r] * KDIM + k0 + j * 8;
        size_t gb = (size_t)(n0 + r) * KDIM + k0 + j * 8;
        cp16(sb + so,             Ah + ga);
        cp16(sb + TILEB + so,     Al + ga);
        cp16(sb + 2 * TILEB + so, Bh + gb);
        cp16(sb + 3 * TILEB + so, Bl + gb);
    }
}

template <int KDIM, int NDIM, bool G1>
__global__ void __launch_bounds__(256, 2)
moe_gemm(const float* __restrict__ bias) {
    const int e = blockIdx.z;
    const int cnt = g_cnt[e];
    const int m0 = blockIdx.y * 128;
    if (m0 >= cnt) return;
    const int n0 = blockIdx.x * 128;
    constexpr int NT = KDIM / 32;

    extern __shared__ char smem[];
    const uint32_t sb = smem_u32(smem);
    const int tid = threadIdx.x, wid = tid >> 5, lane = tid & 31;
    const int warp_m = wid >> 2, warp_n = wid & 3;
    const int g = lane >> 2, tg = lane & 3;
    int* srow = (int*)(smem + 2 * STAGEB);

    if (tid < 128) {
        int rr = min(m0 + tid, cnt - 1);
        srow[tid] = G1 ? g_tok[e][rr] : (e * TOKENS + rr);
    }
    __syncthreads();

    const bf16* Ah = G1 ? g_xh : g_hh;
    const bf16* Al = G1 ? g_xl : g_hl;
    const bf16* Bh = (G1 ? g_w1h : g_w2h) + (size_t)e * NDIM * KDIM;
    const bf16* Bl = (G1 ? g_w1l : g_w2l) + (size_t)e * NDIM * KDIM;

    float acc[4][4][4];
#pragma unroll
    for (int i = 0; i < 4; i++)
#pragma unroll
        for (int j = 0; j < 4; j++)
#pragma unroll
            for (int k = 0; k < 4; k++) acc[i][j][k] = 0.f;

    stage_load<KDIM>(sb, 0, Ah, Al, Bh, Bl, srow, n0, tid);
    cp_commit();

    const int aRowBase = warp_m * 64 + g;
    const int bRowBase = warp_n * 32 + g;

    for (int it = 0; it < NT; it++) {
        cp_wait0();
        __syncthreads();
        if (it + 1 < NT) {
            stage_load<KDIM>(sb + ((it + 1) & 1) * STAGEB, (it + 1) * 32,
                             Ah, Al, Bh, Bl, srow, n0, tid);
            cp_commit();
        }
        const char* st = smem + (it & 1) * STAGEB;
#pragma unroll
        for (int ks = 0; ks < 2; ks++) {
            const int colb = (ks * 16 + tg * 2) * 2;   // byte offset within row
            // B fragments first (16 regs live), then A per-mf (8 regs, short-lived)
            uint32_t bh[4][2], bl[4][2];
#pragma unroll
            for (int nf = 0; nf < 4; nf++) {
                int ro = (bRowBase + nf * 8) * ROWB + colb;
                bh[nf][0] = *(const uint32_t*)(st + 2 * TILEB + ro);
                bh[nf][1] = *(const uint32_t*)(st + 2 * TILEB + ro + 16);
                bl[nf][0] = *(const uint32_t*)(st + 3 * TILEB + ro);
                bl[nf][1] = *(const uint32_t*)(st + 3 * TILEB + ro + 16);
            }
#pragma unroll
            for (int mf = 0; mf < 4; mf++) {
                int ro = (aRowBase + mf * 16) * ROWB + colb;
                uint32_t ah[4], al[4];
                ah[0] = *(const uint32_t*)(st + ro);
                ah[1] = *(const uint32_t*)(st + ro + 8 * ROWB);
                ah[2] = *(const uint32_t*)(st + ro + 16);
                ah[3] = *(const uint32_t*)(st + ro + 8 * ROWB + 16);
                al[0] = *(const uint32_t*)(st + TILEB + ro);
                al[1] = *(const uint32_t*)(st + TILEB + ro + 8 * ROWB);
                al[2] = *(const uint32_t*)(st + TILEB + ro + 16);
                al[3] = *(const uint32_t*)(st + TILEB + ro + 8 * ROWB + 16);
#pragma unroll
                for (int nf = 0; nf < 4; nf++) {
                    MMA_BF16(acc[mf][nf], ah, bh[nf]);
                    MMA_BF16(acc[mf][nf], ah, bl[nf]);
                    MMA_BF16(acc[mf][nf], al, bh[nf]);
                }
            }
        }
        __syncthreads();
    }

    // ---------------- epilogue ----------------
#pragma unroll
    for (int mf = 0; mf < 4; mf++) {
        int r0 = m0 + warp_m * 64 + mf * 16 + g;
        int r1 = r0 + 8;
#pragma unroll
        for (int nf = 0; nf < 4; nf++) {
            int col = n0 + warp_n * 32 + nf * 8 + tg * 2;
            float bv0 = bias[e * NDIM + col];
            float bv1 = bias[e * NDIM + col + 1];
#pragma unroll
            for (int h = 0; h < 2; h++) {
                int r = h ? r1 : r0;
                if (r >= cnt) continue;
                float v0 = acc[mf][nf][2 * h]     + bv0;
                float v1 = acc[mf][nf][2 * h + 1] + bv1;
                if (G1) {
                    v0 = fmaxf(v0, 0.f);
                    v1 = fmaxf(v1, 0.f);
                    __nv_bfloat162 hh, ll;
                    split2(v0, v1, hh, ll);
                    size_t o = ((size_t)(e * TOKENS + r)) * DF + col;
                    *(__nv_bfloat162*)(g_hh + o) = hh;
                    *(__nv_bfloat162*)(g_hl + o) = ll;
                } else {
                    int token = g_tok[e][r];
                    int slot  = g_slot[e][r];
                    float* dst = g_buf + ((size_t)slot * TOKENS + token) * DM + col;
                    *(float2*)dst = make_float2(v0, v1);
                }
            }
        }
    }
}

// ---------------- 4) combine ----------------
__global__ void combine_kernel(float* __restrict__ out) {
    int i = blockIdx.x * blockDim.x + threadIdx.x;
    const float4* b0 = (const float4*)g_buf;
    const float4* b1 = (const float4*)(g_buf + (size_t)TOKENS * DM);
    float4 u = b0[i], v = b1[i];
    ((float4*)out)[i] = make_float4(u.x + v.x, u.y + v.y, u.z + v.z, u.w + v.w);
}

// ---------------- host ----------------
extern "C" void kernel_launch(void* const* d_in, const int* in_sizes, int n_in,
                              void* d_out, int out_size) {
    const float* x  = (const float*)d_in[0];
    const float* Wg = (const float*)d_in[1];
    const float* bg = (const float*)d_in[2];
    const float* W1 = (const float*)d_in[3];
    const float* b1 = (const float*)d_in[4];
    const float* W2 = (const float*)d_in[5];
    const float* b2 = (const float*)d_in[6];
    float* out = (float*)d_out;

    cudaFuncSetAttribute(moe_gemm<DM, DF, true>,
                         cudaFuncAttributeMaxDynamicSharedMemorySize, SMEMB);
    cudaFuncSetAttribute(moe_gemm<DF, DM, false>,
                         cudaFuncAttributeMaxDynamicSharedMemorySize, SMEMB);

    zero_cnt_kernel<<<1, 32>>>();
    route_kernel<<<TOKENS / 8, 256>>>(x, Wg, bg);

    convert_x_kernel<<<TOKENS * DM / 4 / 256, 256>>>(x);
    convert_w_kernel<DM, DF, true><<<dim3(DF / 32, DM / 32, NE), dim3(32, 8)>>>(W1);
    convert_w_kernel<DF, DM, false><<<dim3(DM / 32, DF / 32, NE), dim3(32, 8)>>>(W2);

    // GEMM1: h = relu(gather(x) @ W1[e] + b1[e]) -> g_hh/g_hl
    moe_gemm<DM, DF, true><<<dim3(DF / 128, TOKENS / 128, NE), 256, SMEMB>>>(b1);
    // GEMM2: y = h @ W2[e] + b2[e] -> scatter into g_buf
    moe_gemm<DF, DM, false><<<dim3(DM / 128, TOKENS / 128, NE), 256, SMEMB>>>(b2);

    combine_kernel<<<(TOKENS * DM / 4) / 256, 256>>>(out);
}

// round 6
// speedup vs baseline: 1.7727x; 1.4029x over previous
#include <cuda_runtime.h>
#include <cuda_fp16.h>
#include <cstdint>

#define TOKENS 4096
#define DM 1024
#define DF 4096
#define NE 8

// ---------------- device scratch (static, no runtime alloc) ----------------
__device__ int g_cnt[NE];
__device__ int g_tok[NE][TOKENS];
__device__ int g_slot[NE][TOKENS];
__device__ __align__(16) __half g_xh[(size_t)TOKENS * DM];
__device__ __align__(16) __half g_w1h[(size_t)NE * DF * DM];   // [E][N=DF][K=DM]
__device__ __align__(16) __half g_w1l[(size_t)NE * DF * DM];
__device__ __align__(16) __half g_w2h[(size_t)NE * DM * DF];   // [E][N=DM][K=DF]
__device__ __align__(16) __half g_w2l[(size_t)NE * DM * DF];
__device__ __align__(16) __half g_hh[(size_t)NE * TOKENS * DF];
__device__ __align__(16) float  g_buf[(size_t)2 * TOKENS * DM];

// ---------------- helpers ----------------
__device__ __forceinline__ uint32_t smem_u32(const void* p) {
    uint32_t a;
    asm("{ .reg .u64 t; cvta.to.shared.u64 t, %1; cvt.u32.u64 %0, t; }" : "=r"(a) : "l"(p));
    return a;
}
__device__ __forceinline__ void cp16(uint32_t s, const void* g) {
    asm volatile("cp.async.cg.shared.global [%0], [%1], 16;" :: "r"(s), "l"(g) : "memory");
}
__device__ __forceinline__ void cp_commit() {
    asm volatile("cp.async.commit_group;" ::: "memory");
}
__device__ __forceinline__ void cp_wait0() {
    asm volatile("cp.async.wait_group 0;" ::: "memory");
}
#define MMA_F16(acc, a, b)                                                       \
    asm volatile(                                                                \
        "mma.sync.aligned.m16n8k16.row.col.f32.f16.f16.f32 "                     \
        "{%0,%1,%2,%3},{%4,%5,%6,%7},{%8,%9},{%0,%1,%2,%3};"                     \
        : "+f"((acc)[0]), "+f"((acc)[1]), "+f"((acc)[2]), "+f"((acc)[3])         \
        : "r"((a)[0]), "r"((a)[1]), "r"((a)[2]), "r"((a)[3]),                    \
          "r"((b)[0]), "r"((b)[1]))

// fp32 -> fp16 hi + lo residual
__device__ __forceinline__ void splitf16(float a, __half& h, __half& l) {
    h = __float2half_rn(a);
    l = __float2half_rn(a - __half2float(h));
}

// ---------------- 0) zero counters ----------------
__global__ void zero_cnt_kernel() {
    if (threadIdx.x < NE) g_cnt[threadIdx.x] = 0;
}

// ---------------- 1) routing ----------------
__global__ void route_kernel(const float* __restrict__ x,
                             const float* __restrict__ Wg,
                             const float* __restrict__ bg) {
    int warp = threadIdx.x >> 5;
    int lane = threadIdx.x & 31;
    int token = blockIdx.x * 8 + warp;
    if (token >= TOKENS) return;

    float acc[NE];
#pragma unroll
    for (int e = 0; e < NE; e++) acc[e] = 0.f;
    const float* xrow = x + (size_t)token * DM;
    for (int k = lane; k < DM; k += 32) {
        float xv = xrow[k];
        const float* wr = Wg + (size_t)k * NE;
#pragma unroll
        for (int e = 0; e < NE; e++) acc[e] += xv * wr[e];
    }
#pragma unroll
    for (int e = 0; e < NE; e++)
#pragma unroll
        for (int o = 16; o > 0; o >>= 1)
            acc[e] += __shfl_xor_sync(0xffffffffu, acc[e], o);
    if (lane == 0) {
        float lg[NE];
#pragma unroll
        for (int e = 0; e < NE; e++) lg[e] = acc[e] + bg[e];
        int e0 = 0;
#pragma unroll
        for (int e = 1; e < NE; e++) if (lg[e] > lg[e0]) e0 = e;
        int e1 = (e0 == 0) ? 1 : 0;
#pragma unroll
        for (int e = 0; e < NE; e++) if (e != e0 && lg[e] > lg[e1]) e1 = e;
        int p0 = atomicAdd(&g_cnt[e0], 1);
        g_tok[e0][p0] = token; g_slot[e0][p0] = 0;
        int p1 = atomicAdd(&g_cnt[e1], 1);
        g_tok[e1][p1] = token; g_slot[e1][p1] = 1;
    }
}

// ---------------- 2) converts ----------------
// x: fp32 -> fp16 hi only (A-side; residual term is dropped by design)
__global__ void convert_x_kernel(const float* __restrict__ x) {
    int i = blockIdx.x * blockDim.x + threadIdx.x;   // float4 index
    float4 v = ((const float4*)x)[i];
    __half2 h0, h1;
    h0.x = __float2half_rn(v.x); h0.y = __float2half_rn(v.y);
    h1.x = __float2half_rn(v.z); h1.y = __float2half_rn(v.w);
    ((__half2*)g_xh)[2 * i]     = h0;
    ((__half2*)g_xh)[2 * i + 1] = h1;
}

// transpose + split: W [E][K][N] fp32 -> [E][N][K] fp16 hi/lo
template <int K, int N, bool W1SEL>
__global__ void convert_w_kernel(const float* __restrict__ W) {
    __shared__ float t[32][33];
    __half* Oh = W1SEL ? g_w1h : g_w2h;
    __half* Ol = W1SEL ? g_w1l : g_w2l;
    int e = blockIdx.z;
    int n0 = blockIdx.x * 32, k0 = blockIdx.y * 32;
    int tx = threadIdx.x, ty = threadIdx.y;  // 32 x 8
    const float* Wp = W + (size_t)e * K * N;
#pragma unroll
    for (int i = 0; i < 4; i++)
        t[ty + 8 * i][tx] = Wp[(size_t)(k0 + ty + 8 * i) * N + n0 + tx];
    __syncthreads();
    __half* oh = Oh + (size_t)e * N * K;
    __half* ol = Ol + (size_t)e * N * K;
    int n_l = (threadIdx.y * 4) + (tx >> 3);        // 0..31
    int k_l = (tx & 7) * 2;                          // even k, pairs
#pragma unroll
    for (int rep = 0; rep < 2; rep++) {
        int kk = k_l + rep * 16;
        float v0 = t[kk][n_l];
        float v1 = t[kk + 1][n_l];
        __half2 h, l;
        splitf16(v0, h.x, l.x);
        splitf16(v1, h.y, l.y);
        size_t o = (size_t)(n0 + n_l) * K + k0 + kk;
        *(__half2*)(oh + o) = h;
        *(__half2*)(ol + o) = l;
    }
}

// ---------------- 3) fp16 2-MMA split grouped GEMM ----------------
// BM=128, BN=128, BK=32. 256 threads = 8 warps (2 M x 4 N), warp tile 64x32.
// SMEM stage: A | Bh | Bl, each 128 rows x 40 fp16 (80B padded rows).
// 2-stage cp.async, occupancy 2, low-liveness fragment loop (R5-proven shape).
#define ROWB   80
#define TILEB  (128 * ROWB)          // 10240 B
#define STAGEB (3 * TILEB)           // 30720 B
#define SMEMB  (2 * STAGEB + 512)    // 61952 B; 2 CTAs = 124KB < 228KB

template <int KDIM>
__device__ __forceinline__ void stage_load(uint32_t sb, int k0,
                                           const __half* __restrict__ A,
                                           const __half* __restrict__ Bh,
                                           const __half* __restrict__ Bl,
                                           const int* __restrict__ srow, int n0, int tid) {
#pragma unroll
    for (int half_ = 0; half_ < 2; half_++) {
        int c = tid + half_ * 256;       // 0..511
        int r = c >> 2, j = c & 3;
        uint32_t so = (uint32_t)(r * ROWB + j * 16);
        size_t ga = (size_t)srow[r] * KDIM + k0 + j * 8;
        size_t gb = (size_t)(n0 + r) * KDIM + k0 + j * 8;
        cp16(sb + so,             A + ga);
        cp16(sb + TILEB + so,     Bh + gb);
        cp16(sb + 2 * TILEB + so, Bl + gb);
    }
}

template <int KDIM, int NDIM, bool G1>
__global__ void __launch_bounds__(256, 2)
moe_gemm(const float* __restrict__ bias) {
    const int e = blockIdx.z;
    const int cnt = g_cnt[e];
    const int m0 = blockIdx.y * 128;
    if (m0 >= cnt) return;
    const int n0 = blockIdx.x * 128;
    constexpr int NT = KDIM / 32;

    extern __shared__ char smem[];
    const uint32_t sb = smem_u32(smem);
    const int tid = threadIdx.x, wid = tid >> 5, lane = tid & 31;
    const int warp_m = wid >> 2, warp_n = wid & 3;
    const int g = lane >> 2, tg = lane & 3;
    int* srow = (int*)(smem + 2 * STAGEB);

    if (tid < 128) {
        int rr = min(m0 + tid, cnt - 1);
        srow[tid] = G1 ? g_tok[e][rr] : (e * TOKENS + rr);
    }
    __syncthreads();

    const __half* A  = G1 ? g_xh : g_hh;
    const __half* Bh = (G1 ? g_w1h : g_w2h) + (size_t)e * NDIM * KDIM;
    const __half* Bl = (G1 ? g_w1l : g_w2l) + (size_t)e * NDIM * KDIM;

    float acc[4][4][4];
#pragma unroll
    for (int i = 0; i < 4; i++)
#pragma unroll
        for (int j = 0; j < 4; j++)
#pragma unroll
            for (int k = 0; k < 4; k++) acc[i][j][k] = 0.f;

    stage_load<KDIM>(sb, 0, A, Bh, Bl, srow, n0, tid);
    cp_commit();

    const int aRowBase = warp_m * 64 + g;
    const int bRowBase = warp_n * 32 + g;

    for (int it = 0; it < NT; it++) {
        cp_wait0();
        __syncthreads();
        if (it + 1 < NT) {
            stage_load<KDIM>(sb + ((it + 1) & 1) * STAGEB, (it + 1) * 32,
                             A, Bh, Bl, srow, n0, tid);
            cp_commit();
        }
        const char* st = smem + (it & 1) * STAGEB;
#pragma unroll
        for (int ks = 0; ks < 2; ks++) {
            const int colb = (ks * 16 + tg * 2) * 2;   // byte offset within row
            uint32_t bh[4][2], bl[4][2];
#pragma unroll
            for (int nf = 0; nf < 4; nf++) {
                int ro = (bRowBase + nf * 8) * ROWB + colb;
                bh[nf][0] = *(const uint32_t*)(st + TILEB + ro);
                bh[nf][1] = *(const uint32_t*)(st + TILEB + ro + 16);
                bl[nf][0] = *(const uint32_t*)(st + 2 * TILEB + ro);
                bl[nf][1] = *(const uint32_t*)(st + 2 * TILEB + ro + 16);
            }
#pragma unroll
            for (int mf = 0; mf < 4; mf++) {
                int ro = (aRowBase + mf * 16) * ROWB + colb;
                uint32_t a[4];
                a[0] = *(const uint32_t*)(st + ro);
                a[1] = *(const uint32_t*)(st + ro + 8 * ROWB);
                a[2] = *(const uint32_t*)(st + ro + 16);
                a[3] = *(const uint32_t*)(st + ro + 8 * ROWB + 16);
#pragma unroll
                for (int nf = 0; nf < 4; nf++) {
                    MMA_F16(acc[mf][nf], a, bh[nf]);
                    MMA_F16(acc[mf][nf], a, bl[nf]);
                }
            }
        }
        __syncthreads();
    }

    // ---------------- epilogue ----------------
#pragma unroll
    for (int mf = 0; mf < 4; mf++) {
        int r0 = m0 + warp_m * 64 + mf * 16 + g;
        int r1 = r0 + 8;
#pragma unroll
        for (int nf = 0; nf < 4; nf++) {
            int col = n0 + warp_n * 32 + nf * 8 + tg * 2;
            float bv0 = bias[e * NDIM + col];
            float bv1 = bias[e * NDIM + col + 1];
#pragma unroll
            for (int h = 0; h < 2; h++) {
                int r = h ? r1 : r0;
                if (r >= cnt) continue;
                float v0 = acc[mf][nf][2 * h]     + bv0;
                float v1 = acc[mf][nf][2 * h + 1] + bv1;
                if (G1) {
                    v0 = fmaxf(v0, 0.f);
                    v1 = fmaxf(v1, 0.f);
                    __half2 hh;
                    hh.x = __float2half_rn(v0);
                    hh.y = __float2half_rn(v1);
                    size_t o = ((size_t)(e * TOKENS + r)) * DF + col;
                    *(__half2*)(g_hh + o) = hh;
                } else {
                    int token = g_tok[e][r];
                    int slot  = g_slot[e][r];
                    float* dst = g_buf + ((size_t)slot * TOKENS + token) * DM + col;
                    *(float2*)dst = make_float2(v0, v1);
                }
            }
        }
    }
}

// ---------------- 4) combine ----------------
__global__ void combine_kernel(float* __restrict__ out) {
    int i = blockIdx.x * blockDim.x + threadIdx.x;
    const float4* b0 = (const float4*)g_buf;
    const float4* b1 = (const float4*)(g_buf + (size_t)TOKENS * DM);
    float4 u = b0[i], v = b1[i];
    ((float4*)out)[i] = make_float4(u.x + v.x, u.y + v.y, u.z + v.z, u.w + v.w);
}

// ---------------- host ----------------
extern "C" void kernel_launch(void* const* d_in, const int* in_sizes, int n_in,
                              void* d_out, int out_size) {
    const float* x  = (const float*)d_in[0];
    const float* Wg = (const float*)d_in[1];
    const float* bg = (const float*)d_in[2];
    const float* W1 = (const float*)d_in[3];
    const float* b1 = (const float*)d_in[4];
    const float* W2 = (const float*)d_in[5];
    const float* b2 = (const float*)d_in[6];
    float* out = (float*)d_out;

    cudaFuncSetAttribute(moe_gemm<DM, DF, true>,
                         cudaFuncAttributeMaxDynamicSharedMemorySize, SMEMB);
    cudaFuncSetAttribute(moe_gemm<DF, DM, false>,
                         cudaFuncAttributeMaxDynamicSharedMemorySize, SMEMB);

    zero_cnt_kernel<<<1, 32>>>();
    route_kernel<<<TOKENS / 8, 256>>>(x, Wg, bg);

    convert_x_kernel<<<TOKENS * DM / 4 / 256, 256>>>(x);
    convert_w_kernel<DM, DF, true><<<dim3(DF / 32, DM / 32, NE), dim3(32, 8)>>>(W1);
    convert_w_kernel<DF, DM, false><<<dim3(DM / 32, DF / 32, NE), dim3(32, 8)>>>(W2);

    // GEMM1: h = relu(gather(x) @ W1[e] + b1[e]) -> g_hh (fp16)
    moe_gemm<DM, DF, true><<<dim3(DF / 128, TOKENS / 128, NE), 256, SMEMB>>>(b1);
    // GEMM2: y = h @ W2[e] + b2[e] -> scatter into g_buf
    moe_gemm<DF, DM, false><<<dim3(DM / 128, TOKENS / 128, NE), 256, SMEMB>>>(b2);

    combine_kernel<<<(TOKENS * DM / 4) / 256, 256>>>(out);
}